// round 7
// baseline (speedup 1.0000x reference)
#include <cuda_runtime.h>
#include <math.h>
#include <stdint.h>

#define FULL 0xFFFFFFFFu

// monotone float->u32 key: order(key) == order(float), all non-NaN
__device__ __forceinline__ unsigned f2key(float f) {
    unsigned b = __float_as_uint(f);
    return (b & 0x80000000u) ? ~b : (b | 0x80000000u);
}
__device__ __forceinline__ float key2f(unsigned k) {
    unsigned b = (k & 0x80000000u) ? (k ^ 0x80000000u) : ~k;
    return __uint_as_float(b);
}

#define CE(i, j) { unsigned a_ = s[i], b_ = s[j]; s[i] = umax(a_, b_); s[j] = umin(a_, b_); }

__global__ __launch_bounds__(128, 12)   // target ~40 regs -> 48 warps/SM resident
void topk_route_kernel(const float* __restrict__ logits,
                       const float* __restrict__ bias,
                       float* __restrict__ out, int T)
{
    const int lane = threadIdx.x & 31;
    const int warp = threadIdx.x >> 5;
    const int tb = (blockIdx.x * 4 + warp) * 2;   // 2 tokens per warp
    if (tb >= T) return;

    const unsigned lmlt = (1u << lane) - 1u;      // lanemask_lt
    const bool has2 = (tb + 1) < T;

    // ---- issue ALL loads up front (MLP=4+2) ------------------------------
    // lane l owns experts [8l, 8l+8); all 8 are in group l>>2
    const float* lg0 = logits + (size_t)tb * 256 + lane * 8;
    float4 a0 = *(const float4*)lg0;
    float4 a1 = *(const float4*)(lg0 + 4);
    const float* lg1 = lg0 + 256;
    float4 c0, c1;
    if (has2) { c0 = *(const float4*)lg1; c1 = *(const float4*)(lg1 + 4); }

    const float4* bp = (const float4*)(bias + lane * 8);
    float4 b0 = __ldg(bp), b1 = __ldg(bp + 1);
    float bb[8] = {b0.x, b0.y, b0.z, b0.w, b1.x, b1.y, b1.z, b1.w};

    // passthrough both tokens' logits (fire-and-forget as data lands)
    float* lo0 = out + (size_t)T * 16 + (size_t)tb * 256 + lane * 8;
    *(float4*)lo0 = a0;
    *(float4*)(lo0 + 4) = a1;
    if (has2) {
        *(float4*)(lo0 + 256) = c0;
        *(float4*)(lo0 + 260) = c1;
    }

    #pragma unroll
    for (int it = 0; it < 2; it++) {
        if (it == 1 && !has2) break;
        const int t = tb + it;
        float xx[8];
        if (it == 0) {
            xx[0]=a0.x; xx[1]=a0.y; xx[2]=a0.z; xx[3]=a0.w;
            xx[4]=a1.x; xx[5]=a1.y; xx[6]=a1.z; xx[7]=a1.w;
        } else {
            xx[0]=c0.x; xx[1]=c0.y; xx[2]=c0.z; xx[3]=c0.w;
            xx[4]=c1.x; xx[5]=c1.y; xx[6]=c1.z; xx[7]=c1.w;
        }

        // sigmoid (precise: ids must be exact) + bias -> monotone keys
        unsigned orig[8], s[8];
        #pragma unroll
        for (int i = 0; i < 8; i++) {
            float si = 1.0f / (1.0f + expf(-xx[i]));
            orig[i] = f2key(si + bb[i]);
            s[i] = orig[i];
        }

        // per-lane descending sort (Batcher odd-even, 19 comparators)
        CE(0,1) CE(2,3) CE(4,5) CE(6,7)
        CE(0,2) CE(1,3) CE(4,6) CE(5,7)
        CE(1,2) CE(5,6)
        CE(0,4) CE(1,5) CE(2,6) CE(3,7)
        CE(2,4) CE(3,5)
        CE(1,2) CE(3,4) CE(5,6)

        // group score = top2 sum (per-lane top2 free from sort: s[0], s[1])
        unsigned m1 = s[0], m2 = s[1];
        #pragma unroll
        for (int off = 1; off <= 2; off <<= 1) {
            unsigned o1 = __shfl_xor_sync(FULL, m1, off);
            unsigned o2 = __shfl_xor_sync(FULL, m2, off);
            unsigned l2 = umin(m1, o1);
            m1 = umax(m1, o1);
            m2 = umax(l2, umax(m2, o2));
        }
        float gs = key2f(m1) + key2f(m2);   // identical across each quad

        // broadcast 8 group scores; lane ranks its OWN group (exact jax ties)
        float g[8];
        #pragma unroll
        for (int j = 0; j < 8; j++) g[j] = __shfl_sync(FULL, gs, j * 4);
        int grp = lane >> 2;
        int rank = 0;
        #pragma unroll
        for (int j = 0; j < 8; j++)
            rank += ((g[j] > gs) || (g[j] == gs && j < grp)) ? 1 : 0;
        bool sel = rank < 4;

        // mask unselected groups to key(0.0f)
        #pragma unroll
        for (int i = 0; i < 8; i++) s[i] = sel ? s[i] : 0x80000000u;

        // 8 extraction rounds; record ballot, decode winner lane once after
        unsigned krec = 0, brec = 0;
        #pragma unroll
        for (int r = 0; r < 8; r++) {
            unsigned kmax = __reduce_max_sync(FULL, s[0]);
            bool eq = (s[0] == kmax);
            unsigned bal = __ballot_sync(FULL, eq);
            if (lane == r) { krec = kmax; brec = bal; }
            if (r < 7) {
                bool p = eq && ((bal & lmlt) == 0u);   // lowest-lane winner shifts
                #pragma unroll
                for (int i = 0; i < 7; i++) s[i] = p ? s[i + 1] : s[i];
            }
        }
        int wrec = __ffs((int)brec) - 1;

        // index recovery: lane k finds pos of krec in lane wrec's orig[]
        unsigned gk[8];
        #pragma unroll
        for (int i = 0; i < 8; i++) gk[i] = __shfl_sync(FULL, orig[i], wrec);
        int pos = 7;
        #pragma unroll
        for (int i = 6; i >= 0; i--) pos = (gk[i] == krec) ? i : pos;
        int gidx = (wrec << 3) + pos;

        // weight = unbiased score = biased - bias ; normalize; scale
        float w = key2f(krec) - __ldg(bias + gidx);
        float sum = w;
        sum += __shfl_xor_sync(FULL, sum, 1);
        sum += __shfl_xor_sync(FULL, sum, 2);
        sum += __shfl_xor_sync(FULL, sum, 4);
        float wn = w / sum * 2.5f;

        if (lane < 8) {
            out[(size_t)t * 8 + lane] = wn;
            out[(size_t)T * 8 + (size_t)t * 8 + lane] = (float)gidx;
        }
    }
}

extern "C" void kernel_launch(void* const* d_in, const int* in_sizes, int n_in,
                              void* d_out, int out_size)
{
    // inputs: hidden_states (unused), router_logits [T,256], correction_bias [256]
    const float* logits = (const float*)d_in[1];
    const float* bias   = (const float*)d_in[2];
    float* out = (float*)d_out;

    int T = in_sizes[1] / 256;
    int tok_per_block = 8;                                // 4 warps x 2 tokens
    int blocks = (T + tok_per_block - 1) / tok_per_block; // 2048 for T=16384
    topk_route_kernel<<<blocks, 128>>>(logits, bias, out, T);
}

// round 8
// speedup vs baseline: 1.2888x; 1.2888x over previous
#include <cuda_runtime.h>
#include <math.h>
#include <stdint.h>

#define FULL 0xFFFFFFFFu

// monotone float->u32 key, branchless (SHF.R.S32 + LOP3)
__device__ __forceinline__ unsigned f2key(float f) {
    unsigned b = __float_as_uint(f);
    return b ^ (0x80000000u | (unsigned)((int)b >> 31));
}
__device__ __forceinline__ float key2f(unsigned k) {
    // inverse: if k has sign bit set it was a non-negative float
    unsigned b = (k & 0x80000000u) ? (k ^ 0x80000000u) : ~k;
    return __uint_as_float(b);
}

#define CE(i, j) { unsigned a_ = s[i], b_ = s[j]; s[i] = umax(a_, b_); s[j] = umin(a_, b_); }

__global__ __launch_bounds__(128)
void topk_route_kernel(const float* __restrict__ logits,
                       const float* __restrict__ bias,
                       float* __restrict__ out, int T)
{
    const int lane = threadIdx.x & 31;
    const int warp = threadIdx.x >> 5;
    const int t = blockIdx.x * 4 + warp;
    if (t >= T) return;

    const unsigned lmlt = (1u << lane) - 1u;   // lanemask_lt

    // lane l owns experts [8l, 8l+8); all 8 are in group l>>2
    const float* lg = logits + (size_t)t * 256 + lane * 8;
    float4 x0 = *(const float4*)lg;
    float4 x1 = *(const float4*)(lg + 4);

    // passthrough logits immediately
    float* lo = out + (size_t)T * 16 + (size_t)t * 256 + lane * 8;
    *(float4*)lo = x0;
    *(float4*)(lo + 4) = x1;

    const float4* bp = (const float4*)(bias + lane * 8);
    float4 b0 = __ldg(bp), b1 = __ldg(bp + 1);

    float xx[8] = {x0.x, x0.y, x0.z, x0.w, x1.x, x1.y, x1.z, x1.w};
    float bb[8] = {b0.x, b0.y, b0.z, b0.w, b1.x, b1.y, b1.z, b1.w};

    // sigmoid (precise: ids must be exact) + bias -> monotone keys
    unsigned orig[8], s[8];
    #pragma unroll
    for (int i = 0; i < 8; i++) {
        float si = 1.0f / (1.0f + expf(-xx[i]));
        orig[i] = f2key(si + bb[i]);
        s[i] = orig[i];
    }

    // per-lane descending sort (Batcher odd-even, 19 comparators)
    CE(0,1) CE(2,3) CE(4,5) CE(6,7)
    CE(0,2) CE(1,3) CE(4,6) CE(5,7)
    CE(1,2) CE(5,6)
    CE(0,4) CE(1,5) CE(2,6) CE(3,7)
    CE(2,4) CE(3,5)
    CE(1,2) CE(3,4) CE(5,6)

    // group score = top2 sum (per-lane top2 free from sort: s[0], s[1])
    unsigned m1 = s[0], m2 = s[1];
    #pragma unroll
    for (int off = 1; off <= 2; off <<= 1) {
        unsigned o1 = __shfl_xor_sync(FULL, m1, off);
        unsigned o2 = __shfl_xor_sync(FULL, m2, off);
        unsigned l2 = umin(m1, o1);
        m1 = umax(m1, o1);
        m2 = umax(l2, umax(m2, o2));
    }
    float gs = key2f(m1) + key2f(m2);   // identical across each quad

    // broadcast 8 group scores; lane ranks its OWN group (exact jax ties)
    float g[8];
    #pragma unroll
    for (int j = 0; j < 8; j++) g[j] = __shfl_sync(FULL, gs, j * 4);
    int grp = lane >> 2;
    int rank = 0;
    #pragma unroll
    for (int j = 0; j < 8; j++)
        rank += ((g[j] > gs) || (g[j] == gs && j < grp)) ? 1 : 0;
    bool sel = rank < 4;

    // mask unselected groups to key(0.0f)
    #pragma unroll
    for (int i = 0; i < 8; i++) s[i] = sel ? s[i] : 0x80000000u;

    // 8 extraction rounds; record ballot, decode winner lane once after.
    // brec init 1 (not 0): lanes >= 8 then resolve to lane 0 / a valid gidx,
    // keeping the speculative bias gather in-bounds.
    unsigned krec = 0, brec = 1;
    #pragma unroll
    for (int r = 0; r < 8; r++) {
        unsigned kmax = __reduce_max_sync(FULL, s[0]);
        bool eq = (s[0] == kmax);
        unsigned bal = __ballot_sync(FULL, eq);
        if (lane == r) { krec = kmax; brec = bal; }
        if (r < 7) {
            bool p = eq && ((bal & lmlt) == 0u);   // lowest-lane winner shifts
            #pragma unroll
            for (int i = 0; i < 7; i++) s[i] = p ? s[i + 1] : s[i];
        }
    }
    int wrec = __ffs((int)brec) - 1;

    // index recovery: lane k finds pos of krec in lane wrec's orig[]
    unsigned gk[8];
    #pragma unroll
    for (int i = 0; i < 8; i++) gk[i] = __shfl_sync(FULL, orig[i], wrec);
    int pos = 7;
    #pragma unroll
    for (int i = 6; i >= 0; i--) pos = (gk[i] == krec) ? i : pos;
    int gidx = (wrec << 3) + pos;

    // weight = unbiased score = biased - bias ; normalize (fast div ok); scale
    float w = key2f(krec) - __ldg(bias + gidx);
    float sum = w;
    sum += __shfl_xor_sync(FULL, sum, 1);
    sum += __shfl_xor_sync(FULL, sum, 2);
    sum += __shfl_xor_sync(FULL, sum, 4);
    float wn = __fdividef(w, sum) * 2.5f;

    if (lane < 8) {
        out[(size_t)t * 8 + lane] = wn;
        out[(size_t)T * 8 + (size_t)t * 8 + lane] = (float)gidx;
    }
}

extern "C" void kernel_launch(void* const* d_in, const int* in_sizes, int n_in,
                              void* d_out, int out_size)
{
    // inputs: hidden_states (unused), router_logits [T,256], correction_bias [256]
    const float* logits = (const float*)d_in[1];
    const float* bias   = (const float*)d_in[2];
    float* out = (float*)d_out;

    int T = in_sizes[1] / 256;
    int blocks = (T + 3) / 4;              // 1 token per warp, 4 warps per block
    topk_route_kernel<<<blocks, 128>>>(logits, bias, out, T);
}